// round 8
// baseline (speedup 1.0000x reference)
#include <cuda_runtime.h>
#include <cuda_bf16.h>

// EmbeddingSumConcat: out[b, f*E+e] = sum_{l < lengths[b,f]} tables[f, ids[b,f,l], e]
// B=4096, F=32, V=100000, L=20, E=64. ids/lengths int32 (JAX x64 disabled),
// tables/out fp32.
//
// R8: decouple gather MLP from registers via cp.async.cg staging to smem.
// Each thread issues up to 20 predicated 16B async copies (no dst registers,
// no depth cap), waits once, then sums from shared. 40KB smem/CTA -> 5 CTAs
// (20 warps/SM), but per-SM outstanding loads go from ~290 to thousands.

#define EB_B 4096
#define EB_F 32
#define EB_V 100000
#define EB_L 20
#define EB_E 64
#define EB_V4 (EB_E / 4)     // 16 float4 per row

__global__ __launch_bounds__(128) void embbag_kernel(
    const int*    __restrict__ ids,      // int32 [B, F, L]
    const int*    __restrict__ lengths,  // int32 [B, F]
    const float4* __restrict__ tables,   // fp32  [F, V, E/4]
    float4*       __restrict__ out)      // fp32  [B, F, E/4]
{
    __shared__ float4 stage[EB_L][128];  // [l][thread], conflict-free readback

    int t   = threadIdx.x;
    int tid = blockIdx.x * 128 + t;                 // 0 .. B*F*16-1
    int v    = tid & (EB_V4 - 1);                   // float4 lane in row (0..15)
    int cell = tid >> 4;                            // f-major: cell = f*B + b
    int b    = cell & (EB_B - 1);                   // B = 4096 = 2^12
    int f    = cell >> 12;

    size_t bf = (size_t)b * EB_F + f;
    int n = lengths[bf];                            // 0..20
    const float4* base = tables + (size_t)f * EB_V * EB_V4;

    // Ids for this cell: 80 bytes, 16B-aligned (bf*80). 5x int4 loads,
    // hardware-broadcast across the 16 lanes of the cell.
    const int4* idp4 = (const int4*)(ids + bf * EB_L);
    int idbuf[EB_L];
#pragma unroll
    for (int q = 0; q < EB_L / 4; q++) {
        int4 w = __ldg(&idp4[q]);
        idbuf[q * 4 + 0] = w.x;
        idbuf[q * 4 + 1] = w.y;
        idbuf[q * 4 + 2] = w.z;
        idbuf[q * 4 + 3] = w.w;
    }

    // Issue all gathers as 16B async copies: no dst registers, so all ~n
    // loads are in flight simultaneously regardless of register budget.
    unsigned sbase = (unsigned)__cvta_generic_to_shared(&stage[0][t]);
#pragma unroll
    for (int l = 0; l < EB_L; l++) {
        if (l < n) {
            const float4* gp = &base[(size_t)idbuf[l] * EB_V4 + v];
            unsigned sp = sbase + l * 128 * (unsigned)sizeof(float4);
            asm volatile("cp.async.cg.shared.global [%0], [%1], 16;"
                         :: "r"(sp), "l"(gp));
        }
    }
    asm volatile("cp.async.wait_all;" ::: "memory");

    // Sum own staged rows (per-thread data; no block sync needed).
    float4 acc = make_float4(0.f, 0.f, 0.f, 0.f);
#pragma unroll
    for (int l = 0; l < EB_L; l++) {
        if (l < n) {
            float4 r = stage[l][t];
            acc.x += r.x; acc.y += r.y; acc.z += r.z; acc.w += r.w;
        }
    }

    // Streaming store: written once, never re-read; keep table rows in L2.
    __stcs(&out[bf * EB_V4 + v], acc);
}

extern "C" void kernel_launch(void* const* d_in, const int* in_sizes, int n_in,
                              void* d_out, int out_size) {
    const int*    ids     = (const int*)d_in[0];    // int32 [B,F,L]
    const int*    lengths = (const int*)d_in[1];    // int32 [B,F]
    const float4* tables  = (const float4*)d_in[2]; // fp32  [F,V,E]
    float4*       out     = (float4*)d_out;         // fp32  [B,F*E]

    int total = EB_B * EB_F * EB_V4;                // 2,097,152 threads
    embbag_kernel<<<total / 128, 128>>>(ids, lengths, tables, out);
}

// round 9
// speedup vs baseline: 1.2444x; 1.2444x over previous
#include <cuda_runtime.h>
#include <cuda_bf16.h>

// EmbeddingSumConcat: out[b, f*E+e] = sum_{l < lengths[b,f]} tables[f, ids[b,f,l], e]
// B=4096, F=32, V=100000, L=20, E=64. ids/lengths int32 (JAX x64 disabled),
// tables/out fp32.
//
// R9: warp-per-cell, float2 lanes. Each LDG.64 warp-instruction covers exactly
// ONE 256B table row (32 lanes x 8B), so each random row gets its own
// scoreboard completion instead of two rows sharing one (R7's LDG.128 had
// lanes 0-15 on row A, 16-31 on row B; the slower row gated both).

#define EB_B 4096
#define EB_F 32
#define EB_V 100000
#define EB_L 20
#define EB_E 64
#define EB_V2 (EB_E / 2)     // 32 float2 per row

__global__ __launch_bounds__(128, 16) void embbag_kernel(
    const int*    __restrict__ ids,      // int32 [B, F, L]
    const int*    __restrict__ lengths,  // int32 [B, F]
    const float2* __restrict__ tables,   // fp32  [F, V, E/2]
    float2*       __restrict__ out)      // fp32  [B, F, E/2]
{
    int tid = blockIdx.x * 128 + threadIdx.x;       // 0 .. B*F*32-1
    int v    = tid & (EB_V2 - 1);                   // float2 lane in row (0..31)
    int cell = tid >> 5;                            // f-major: cell = f*B + b
    int b    = cell & (EB_B - 1);                   // B = 4096 = 2^12
    int f    = cell >> 12;

    size_t bf = (size_t)b * EB_F + f;
    int n = lengths[bf];                            // 0..20
    const float2* base = tables + (size_t)f * EB_V * EB_V2;

    // Ids for this cell: 80 bytes, 16B-aligned (bf*80). 5x int4 loads,
    // hardware-broadcast across the 32 lanes of the cell.
    const int4* idp4 = (const int4*)(ids + bf * EB_L);
    int idbuf[EB_L];
#pragma unroll
    for (int q = 0; q < EB_L / 4; q++) {
        int4 w = __ldg(&idp4[q]);
        idbuf[q * 4 + 0] = w.x;
        idbuf[q * 4 + 1] = w.y;
        idbuf[q * 4 + 2] = w.z;
        idbuf[q * 4 + 3] = w.w;
    }

    float2 acc = make_float2(0.f, 0.f);
#pragma unroll
    for (int l = 0; l < EB_L; l++) {
        if (l < n) {
            float2 r = __ldg(&base[(size_t)idbuf[l] * EB_V2 + v]);
            acc.x += r.x; acc.y += r.y;
        }
    }

    // Streaming store: written once, never re-read; keep table rows in L2.
    __stcs(&out[bf * EB_V2 + v], acc);
}

extern "C" void kernel_launch(void* const* d_in, const int* in_sizes, int n_in,
                              void* d_out, int out_size) {
    const int*    ids     = (const int*)d_in[0];    // int32 [B,F,L]
    const int*    lengths = (const int*)d_in[1];    // int32 [B,F]
    const float2* tables  = (const float2*)d_in[2]; // fp32  [F,V,E]
    float2*       out     = (float2*)d_out;         // fp32  [B,F*E]

    int total = EB_B * EB_F * EB_V2;                // 4,194,304 threads
    embbag_kernel<<<total / 128, 128>>>(ids, lengths, tables, out);
}

// round 10
// speedup vs baseline: 1.2850x; 1.0326x over previous
#include <cuda_runtime.h>
#include <cuda_bf16.h>

// EmbeddingSumConcat: out[b, f*E+e] = sum_{l < lengths[b,f]} tables[f, ids[b,f,l], e]
// B=4096, F=32, V=100000, L=20, E=64. ids/lengths int32 (JAX x64 disabled),
// tables/out fp32.
//
// R10: Blackwell LDG.256 gathers. 8 lanes per cell, each lane loads 32B via
// ld.global.nc.L2::evict_last.v8.b32 — one warp-instruction = one full 256B
// row, half the wavefronts/instructions of R7, double in-flight bytes per
// scoreboard entry. evict_last keeps the reusable table stream resident in L2
// while __stcs output stores evict first.

#define EB_B 4096
#define EB_F 32
#define EB_V 100000
#define EB_L 20
#define EB_E 64
#define EB_V8 (EB_E / 8)     // 8 lanes of 8 floats (32B) per row

__global__ __launch_bounds__(128, 8) void embbag_kernel(
    const int*   __restrict__ ids,      // int32 [B, F, L]
    const int*   __restrict__ lengths,  // int32 [B, F]
    const float* __restrict__ tables,   // fp32  [F, V, E]
    float*       __restrict__ out)      // fp32  [B, F, E]
{
    int tid = blockIdx.x * 128 + threadIdx.x;       // 0 .. B*F*8-1
    int v    = tid & (EB_V8 - 1);                   // 32B lane in row (0..7)
    int cell = tid >> 3;                            // f-major: cell = f*B + b
    int b    = cell & (EB_B - 1);                   // B = 4096 = 2^12
    int f    = cell >> 12;

    size_t bf = (size_t)b * EB_F + f;
    int n = lengths[bf];                            // 0..20
    const float* base = tables + (size_t)f * EB_V * EB_E + v * 8;

    // Ids for this cell: 80 bytes, 16B-aligned (bf*80). 5x int4 loads,
    // hardware-broadcast across the 8 lanes of the cell.
    const int4* idp4 = (const int4*)(ids + bf * EB_L);
    int idbuf[EB_L];
#pragma unroll
    for (int q = 0; q < EB_L / 4; q++) {
        int4 w = __ldg(&idp4[q]);
        idbuf[q * 4 + 0] = w.x;
        idbuf[q * 4 + 1] = w.y;
        idbuf[q * 4 + 2] = w.z;
        idbuf[q * 4 + 3] = w.w;
    }

    float a0 = 0.f, a1 = 0.f, a2 = 0.f, a3 = 0.f;
    float a4 = 0.f, a5 = 0.f, a6 = 0.f, a7 = 0.f;
#pragma unroll
    for (int l = 0; l < EB_L; l++) {
        if (l < n) {
            const float* p = base + (size_t)idbuf[l] * EB_E;
            unsigned u0, u1, u2, u3, u4, u5, u6, u7;
            asm volatile(
                "ld.global.nc.L2::evict_last.v8.b32 "
                "{%0,%1,%2,%3,%4,%5,%6,%7}, [%8];"
                : "=r"(u0), "=r"(u1), "=r"(u2), "=r"(u3),
                  "=r"(u4), "=r"(u5), "=r"(u6), "=r"(u7)
                : "l"(p));
            a0 += __uint_as_float(u0); a1 += __uint_as_float(u1);
            a2 += __uint_as_float(u2); a3 += __uint_as_float(u3);
            a4 += __uint_as_float(u4); a5 += __uint_as_float(u5);
            a6 += __uint_as_float(u6); a7 += __uint_as_float(u7);
        }
    }

    // Streaming stores: written once, never re-read.
    float4* op = (float4*)(out + bf * EB_E + v * 8);
    __stcs(&op[0], make_float4(a0, a1, a2, a3));
    __stcs(&op[1], make_float4(a4, a5, a6, a7));
}

extern "C" void kernel_launch(void* const* d_in, const int* in_sizes, int n_in,
                              void* d_out, int out_size) {
    const int*   ids     = (const int*)d_in[0];     // int32 [B,F,L]
    const int*   lengths = (const int*)d_in[1];     // int32 [B,F]
    const float* tables  = (const float*)d_in[2];   // fp32  [F,V,E]
    float*       out     = (float*)d_out;           // fp32  [B,F*E]

    int total = EB_B * EB_F * EB_V8;                // 1,048,576 threads
    embbag_kernel<<<total / 128, 128>>>(ids, lengths, tables, out);
}